// round 12
// baseline (speedup 1.0000x reference)
#include <cuda_runtime.h>
#include <cuda_fp16.h>
#include <math.h>

// ---------------- problem constants ----------------
#define NE     100000
#define NU     50000
#define NTOT   (NE+NU)
#define NEDGE  2000000
#define NNZV   1000000
#define CH     128
#define C4     32
#define CHH2   64
#define RR0    42033
#define RR1    44630
#define RM     (RR1-RR0)     // 2597
#define RMP    2624
#define NREL   25
#define NHOPS  3
#define SK     8
#define NSCAN  147
#define EBLK   (NE/8)
#define UBLK   (NU/8)
#define NBM    41            // (RMP+63)/64

// ---------------- device scratch ----------------
__device__ __half g_Eh0[NE*CH];            // fp16 input entity table
__device__ __half g_H1[NE*CH];             // hop-1/2 entity outputs
__device__ __half g_H2[NE*CH];
__device__ __half g_U1[NU*CH];             // hop-1/2 user outputs
__device__ __half g_U2[NU*CH];
__device__ __half g_Ah[RMP*RMP];
__device__ float g_regp[SK*RM*CH];
__device__ int   g_sync[NBM];              // split-K completion counters (self-reset)
__device__ int   g_cnt[NTOT];
__device__ int   g_rowptr[NTOT+1];
__device__ int   g_cursor[NTOT];
__device__ int   g_pack[NEDGE];
__device__ int   g_ucol[NNZV];
__device__ float g_uval[NNZV];
__device__ unsigned long long g_lb[NSCAN];

// ---------------- helpers ----------------
__device__ __forceinline__ unsigned packh2(float x, float y) {
    __half2 t = __floats2half2_rn(x, y);
    return *reinterpret_cast<unsigned*>(&t);
}
__device__ __forceinline__ uint2 f4toh4(float4 v) {
    uint2 o; o.x = packh2(v.x, v.y); o.y = packh2(v.z, v.w);
    return o;
}
__device__ __forceinline__ float4 h4tof4(uint2 u) {
    __half2 a = *reinterpret_cast<__half2*>(&u.x);
    __half2 b = *reinterpret_cast<__half2*>(&u.y);
    float2 fa = __half22float2(a), fb = __half22float2(b);
    return make_float4(fa.x, fa.y, fb.x, fb.y);
}
__device__ __forceinline__ void cpa16(void* dst, const void* src) {
    unsigned d = (unsigned)__cvta_generic_to_shared(dst);
    asm volatile("cp.async.cg.shared.global [%0],[%1],16;\n" :: "r"(d), "l"(src));
}
#define CP_COMMIT() asm volatile("cp.async.commit_group;\n")
#define CP_WAIT1()  asm volatile("cp.async.wait_group 1;\n")
#define F4ADD(A,B) A.x+=B.x; A.y+=B.y; A.z+=B.z; A.w+=B.w;

// ---------------- fused setup: count + cvtA + cvtE ----------------
#define NCVE (NE*C4)
#define NCVA (RMP*RMP/4)
#define NSETUP (NEDGE + NNZV + NCVE + NCVA)

__global__ void k_setup(const int* __restrict__ ehead, const int* __restrict__ irows,
                        const float* __restrict__ rwm, const float4* __restrict__ E0) {
    int i = blockIdx.x * blockDim.x + threadIdx.x;
    if (i < NEDGE) {
        atomicAdd(&g_cnt[ehead[i]], 1);
    } else if (i < NEDGE + NNZV) {
        atomicAdd(&g_cnt[NE + irows[i - NEDGE]], 1);
    } else if (i < NEDGE + NNZV + NCVE) {
        int j = i - (NEDGE + NNZV);
        reinterpret_cast<uint2*>(g_Eh0)[j] = f4toh4(E0[j]);
    } else if (i < NSETUP) {
        int j = i - (NEDGE + NNZV + NCVE);
        int r = j / (RMP / 4), c = (j % (RMP / 4)) * 4;
        float v0 = 0, v1 = 0, v2 = 0, v3 = 0;
        if (r < RM) {
            const float* row = rwm + (size_t)r * RM;
            if (c + 0 < RM) v0 = row[c + 0];
            if (c + 1 < RM) v1 = row[c + 1];
            if (c + 2 < RM) v2 = row[c + 2];
            if (c + 3 < RM) v3 = row[c + 3];
        }
        *reinterpret_cast<uint2*>(&g_Ah[(size_t)r * RMP + c]) =
            f4toh4(make_float4(v0, v1, v2, v3));
    }
}

// ---------------- decoupled-lookback exclusive scan (self-resets g_cnt) ----------------
__global__ __launch_bounds__(1024)
void k_scan_lb() {
    __shared__ int s[1024];
    __shared__ int s_prefix;
    int b = blockIdx.x, t = threadIdx.x;
    int i = b * 1024 + t;
    int v = (i < NTOT) ? g_cnt[i] : 0;
    if (i < NTOT) g_cnt[i] = 0;
    s[t] = v;
    __syncthreads();
    #pragma unroll
    for (int off = 1; off < 1024; off <<= 1) {
        int tmp = (t >= off) ? s[t - off] : 0;
        __syncthreads();
        s[t] += tmp;
        __syncthreads();
    }
    int incl = s[t];
    int total = s[1023];
    if (t == 0) {
        if (b == 0) {
            atomicExch(&g_lb[0], (2ULL << 32) | (unsigned)total);
            s_prefix = 0;
        } else {
            atomicExch(&g_lb[b], (1ULL << 32) | (unsigned)total);
            long long ex = 0;
            int idx = b - 1;
            while (true) {
                unsigned long long pk;
                do { pk = atomicAdd(&g_lb[idx], 0ULL); } while ((pk >> 32) == 0);
                ex += (unsigned)pk;
                if ((pk >> 32) == 2ULL) break;
                idx--;
            }
            atomicExch(&g_lb[b], (2ULL << 32) | (unsigned)(ex + total));
            s_prefix = (int)ex;
        }
    }
    __syncthreads();
    int excl = s_prefix + incl - v;
    if (i < NTOT) { g_rowptr[i] = excl; g_cursor[i] = excl; }
    if (i == NTOT - 1) g_rowptr[NTOT] = NEDGE + NNZV;
}

__global__ void k_fill(const int* __restrict__ ehead, const int* __restrict__ etail,
                       const int* __restrict__ etype, const int* __restrict__ irows,
                       const int* __restrict__ icols, const float* __restrict__ ivals) {
    int i = blockIdx.x * blockDim.x + threadIdx.x;
    if (i < NSCAN) g_lb[i] = 0;
    if (i < NEDGE) {
        int pos = atomicAdd(&g_cursor[ehead[i]], 1);
        g_pack[pos] = etail[i] | ((etype[i] - 1) << 17);
    } else if (i < NEDGE + NNZV) {
        int k = i - NEDGE;
        int pos = atomicAdd(&g_cursor[NE + irows[k]], 1) - NEDGE;
        g_ucol[pos] = icols[k];
        g_uval[pos] = ivals[k];
    }
}

// ---------------- fp16 tensor-core region GEMM + fused split-K tail blend --------------
__device__ __forceinline__ void ldsm4(unsigned* r, const void* p) {
    unsigned a = (unsigned)__cvta_generic_to_shared(p);
    asm volatile("ldmatrix.sync.aligned.m8n8.x4.shared.b16 {%0,%1,%2,%3},[%4];"
        : "=r"(r[0]), "=r"(r[1]), "=r"(r[2]), "=r"(r[3]) : "r"(a));
}
__device__ __forceinline__ void ldsm4t(unsigned* r, const void* p) {
    unsigned a = (unsigned)__cvta_generic_to_shared(p);
    asm volatile("ldmatrix.sync.aligned.m8n8.x4.trans.shared.b16 {%0,%1,%2,%3},[%4];"
        : "=r"(r[0]), "=r"(r[1]), "=r"(r[2]), "=r"(r[3]) : "r"(a));
}
__device__ __forceinline__ void mma_f16(float* d, const unsigned* a, const unsigned* b) {
    asm volatile("mma.sync.aligned.m16n8k16.row.col.f32.f16.f16.f32 "
        "{%0,%1,%2,%3},{%4,%5,%6,%7},{%8,%9},{%0,%1,%2,%3};"
        : "+f"(d[0]), "+f"(d[1]), "+f"(d[2]), "+f"(d[3])
        : "r"(a[0]), "r"(a[1]), "r"(a[2]), "r"(a[3]), "r"(b[0]), "r"(b[1]));
}

#define SA_STR 40
#define SB_STR 136

__global__ __launch_bounds__(256)
void k_gemm_mma(const __half* __restrict__ Bsrc, __half2* __restrict__ EhBlend) {
    __shared__ __align__(16) __half sA[2][64 * SA_STR];
    __shared__ __align__(16) __half sB[2][32 * SB_STR];
    __shared__ int s_done;
    int bm = blockIdx.x * 64;
    int sk = blockIdx.y;
    int kb = sk * 320;
    int ke = (sk == SK - 1) ? RMP : kb + 320;
    int iters = (ke - kb) >> 5;
    int tid = threadIdx.x, lane = tid & 31, w = tid >> 5;
    int wm = (w >> 1) * 16, wn = (w & 1) * 64;

    float acc[8][4];
    #pragma unroll
    for (int t = 0; t < 8; t++) { acc[t][0] = acc[t][1] = acc[t][2] = acc[t][3] = 0.f; }

    auto load_stage = [&](int s, int k0) {
        {
            int r = tid >> 2, c = (tid & 3) * 8;
            cpa16(&sA[s][r * SA_STR + c], &g_Ah[(size_t)(bm + r) * RMP + k0 + c]);
        }
        #pragma unroll
        for (int i2 = 0; i2 < 2; i2++) {
            int e = tid + i2 * 256;
            int r = e >> 4, c = (e & 15) * 8;
            cpa16(&sB[s][r * SB_STR + c], &Bsrc[(size_t)(k0 + r) * CH + c]);
        }
    };

    load_stage(0, kb);
    CP_COMMIT();

    for (int it = 0; it < iters; it++) {
        if (it + 1 < iters) load_stage((it + 1) & 1, kb + (it + 1) * 32);
        CP_COMMIT();
        CP_WAIT1();
        __syncthreads();
        int s = it & 1;
        #pragma unroll
        for (int kk = 0; kk < 32; kk += 16) {
            unsigned a[4];
            ldsm4(a, &sA[s][(wm + (lane & 15)) * SA_STR + kk + (lane >> 4) * 8]);
            #pragma unroll
            for (int nt = 0; nt < 4; nt++) {
                unsigned b[4];
                ldsm4t(b, &sB[s][(kk + (lane & 15)) * SB_STR + wn + nt * 16 + (lane >> 4) * 8]);
                mma_f16(acc[nt * 2],     a, b);
                mma_f16(acc[nt * 2 + 1], a, b + 2);
            }
        }
        __syncthreads();
    }

    float* C = g_regp + (size_t)sk * RM * CH;
    int g = lane >> 2, tig = lane & 3;
    #pragma unroll
    for (int t = 0; t < 8; t++) {
        int row = bm + wm + g, col = wn + t * 8 + tig * 2;
        if (row < RM)
            *reinterpret_cast<float2*>(&C[(size_t)row * CH + col]) = make_float2(acc[t][0], acc[t][1]);
        if (row + 8 < RM)
            *reinterpret_cast<float2*>(&C[(size_t)(row + 8) * CH + col]) = make_float2(acc[t][2], acc[t][3]);
    }

    // ---- split-K completion: last block for this bm sums partials + blends in place ----
    __threadfence();
    __syncthreads();
    if (tid == 0) s_done = atomicAdd(&g_sync[blockIdx.x], 1);
    __syncthreads();
    if (s_done == SK - 1) {
        // blend rows [bm, min(bm+64, RM)) : E = 0.8*E + 0.2*sum_s partial
        for (int e = tid; e < 64 * CHH2; e += 256) {
            int lr = e >> 6;            // local row 0..63
            int col = e & 63;           // half2 column
            int r = bm + lr;
            if (r < RM) {
                int fi = r * CH + col * 2;
                float sx = 0.f, sy = 0.f;
                #pragma unroll
                for (int s = 0; s < SK; s++) {
                    float2 p = *reinterpret_cast<const float2*>(&g_regp[(size_t)s * RM * CH + fi]);
                    sx += p.x; sy += p.y;
                }
                float2 ef = __half22float2(EhBlend[(size_t)(RR0 + r) * CHH2 + col]);
                EhBlend[(size_t)(RR0 + r) * CHH2 + col] =
                    __floats2half2_rn(0.8f * ef.x + 0.2f * sx, 0.8f * ef.y + 0.2f * sy);
            }
        }
        if (tid == 0) g_sync[blockIdx.x] = 0;   // self-reset for graph replay / next hop
    }
}

// ---------------- fused aggregate (frozen r9 loop) + folded final residual ------------
__global__ __launch_bounds__(256)
void k_agg(const uint2* __restrict__ E, uint2* __restrict__ Enext,
           uint2* __restrict__ Uout,
           float4* __restrict__ resE, float4* __restrict__ outU,
           const float4* __restrict__ W,
           const float4* __restrict__ E0f, const float4* __restrict__ U0f,
           const uint2* __restrict__ H1v, const uint2* __restrict__ H2v,
           const uint2* __restrict__ U1v, const uint2* __restrict__ U2v,
           int first, int last) {
    int lane = threadIdx.x & 31;
    int wline = threadIdx.x >> 5;

    if (blockIdx.x < EBLK) {
        __shared__ float4 sW[NREL * C4];
        for (int e = threadIdx.x; e < NREL * C4; e += 256) sW[e] = W[e];
        __syncthreads();

        int row = blockIdx.x * 8 + wline;
        int start = g_rowptr[row];
        int end   = g_rowptr[row + 1];

        float4 a0 = make_float4(0,0,0,0), a1 = make_float4(0,0,0,0);
        for (int base = start; base < end; base += 32) {
            int m = min(32, end - base);
            int p = (lane < m) ? g_pack[base + lane] : 0;
            int j = 0;
            for (; j + 4 <= m; j += 4) {
                int p0 = __shfl_sync(0xffffffffu, p, j);
                int p1 = __shfl_sync(0xffffffffu, p, j + 1);
                int p2 = __shfl_sync(0xffffffffu, p, j + 2);
                int p3 = __shfl_sync(0xffffffffu, p, j + 3);
                float4 e0 = h4tof4(E[(p0 & 0x1FFFF) * C4 + lane]);
                float4 e1 = h4tof4(E[(p1 & 0x1FFFF) * C4 + lane]);
                float4 e2 = h4tof4(E[(p2 & 0x1FFFF) * C4 + lane]);
                float4 e3 = h4tof4(E[(p3 & 0x1FFFF) * C4 + lane]);
                float4 w0 = sW[(p0 >> 17) * C4 + lane];
                float4 w1 = sW[(p1 >> 17) * C4 + lane];
                float4 w2 = sW[(p2 >> 17) * C4 + lane];
                float4 w3 = sW[(p3 >> 17) * C4 + lane];
                a0.x += e0.x*w0.x; a0.y += e0.y*w0.y; a0.z += e0.z*w0.z; a0.w += e0.w*w0.w;
                a1.x += e1.x*w1.x; a1.y += e1.y*w1.y; a1.z += e1.z*w1.z; a1.w += e1.w*w1.w;
                a0.x += e2.x*w2.x; a0.y += e2.y*w2.y; a0.z += e2.z*w2.z; a0.w += e2.w*w2.w;
                a1.x += e3.x*w3.x; a1.y += e3.y*w3.y; a1.z += e3.z*w3.z; a1.w += e3.w*w3.w;
            }
            for (; j < m; j++) {
                int pj = __shfl_sync(0xffffffffu, p, j);
                float4 ev = h4tof4(E[(pj & 0x1FFFF) * C4 + lane]);
                float4 w  = sW[(pj >> 17) * C4 + lane];
                a0.x += ev.x*w.x; a0.y += ev.y*w.y; a0.z += ev.z*w.z; a0.w += ev.w*w.w;
            }
        }
        float4 acc = make_float4(a0.x+a1.x, a0.y+a1.y, a0.z+a1.z, a0.w+a1.w);
        int cnt = end - start;
        float inv = cnt ? (1.f / (float)cnt) : 0.f;
        acc.x *= inv; acc.y *= inv; acc.z *= inv; acc.w *= inv;

        float ss = acc.x*acc.x + acc.y*acc.y + acc.z*acc.z + acc.w*acc.w;
        #pragma unroll
        for (int o = 16; o; o >>= 1) ss += __shfl_xor_sync(0xffffffffu, ss, o);
        float scale = 1.f / fmaxf(sqrtf(ss), 1e-12f);
        float4 o4 = make_float4(acc.x*scale, acc.y*scale, acc.z*scale, acc.w*scale);

        int idx = row * C4 + lane;
        bool region = (row >= RR0 && row < RR1);
        if (!last) {
            Enext[idx] = f4toh4(o4);
            if (region) {   // eager residual: hop-buffer copy gets blended next hop
                float4 rv = first ? E0f[idx] : resE[idx];
                F4ADD(rv, o4);
                resE[idx] = rv;
            }
        } else {            // final hop: write out = residual + o directly
            float4 rv;
            if (region) {
                rv = resE[idx];
            } else {
                rv = E0f[idx];
                float4 h1 = h4tof4(H1v[idx]);
                float4 h2 = h4tof4(H2v[idx]);
                F4ADD(rv, h1); F4ADD(rv, h2);
            }
            F4ADD(rv, o4);
            resE[idx] = rv;
        }
    } else {
        int row = (blockIdx.x - EBLK) * 8 + wline;
        int start = g_rowptr[NE + row]     - NEDGE;
        int end   = g_rowptr[NE + row + 1] - NEDGE;

        float4 a0 = make_float4(0,0,0,0), a1 = make_float4(0,0,0,0);
        for (int base = start; base < end; base += 32) {
            int m = min(32, end - base);
            int   c = (lane < m) ? g_ucol[base + lane] : 0;
            float v = (lane < m) ? g_uval[base + lane] : 0.f;
            int j = 0;
            for (; j + 4 <= m; j += 4) {
                int   c0 = __shfl_sync(0xffffffffu, c, j);
                int   c1 = __shfl_sync(0xffffffffu, c, j + 1);
                int   c2 = __shfl_sync(0xffffffffu, c, j + 2);
                int   c3 = __shfl_sync(0xffffffffu, c, j + 3);
                float v0 = __shfl_sync(0xffffffffu, v, j);
                float v1 = __shfl_sync(0xffffffffu, v, j + 1);
                float v2 = __shfl_sync(0xffffffffu, v, j + 2);
                float v3 = __shfl_sync(0xffffffffu, v, j + 3);
                float4 e0 = h4tof4(E[c0 * C4 + lane]);
                float4 e1 = h4tof4(E[c1 * C4 + lane]);
                float4 e2 = h4tof4(E[c2 * C4 + lane]);
                float4 e3 = h4tof4(E[c3 * C4 + lane]);
                a0.x += v0*e0.x; a0.y += v0*e0.y; a0.z += v0*e0.z; a0.w += v0*e0.w;
                a1.x += v1*e1.x; a1.y += v1*e1.y; a1.z += v1*e1.z; a1.w += v1*e1.w;
                a0.x += v2*e2.x; a0.y += v2*e2.y; a0.z += v2*e2.z; a0.w += v2*e2.w;
                a1.x += v3*e3.x; a1.y += v3*e3.y; a1.z += v3*e3.z; a1.w += v3*e3.w;
            }
            for (; j < m; j++) {
                int   cj = __shfl_sync(0xffffffffu, c, j);
                float vj = __shfl_sync(0xffffffffu, v, j);
                float4 ev = h4tof4(E[cj * C4 + lane]);
                a0.x += vj*ev.x; a0.y += vj*ev.y; a0.z += vj*ev.z; a0.w += vj*ev.w;
            }
        }
        float4 acc = make_float4(a0.x+a1.x, a0.y+a1.y, a0.z+a1.z, a0.w+a1.w);
        float ss = acc.x*acc.x + acc.y*acc.y + acc.z*acc.z + acc.w*acc.w;
        #pragma unroll
        for (int o = 16; o; o >>= 1) ss += __shfl_xor_sync(0xffffffffu, ss, o);
        float scale = 1.f / fmaxf(sqrtf(ss), 1e-12f);
        float4 o4 = make_float4(acc.x*scale, acc.y*scale, acc.z*scale, acc.w*scale);

        int idx = row * C4 + lane;
        if (!last) {
            Uout[idx] = f4toh4(o4);
        } else {
            float4 rv = U0f[idx];
            float4 u1 = h4tof4(U1v[idx]);
            float4 u2 = h4tof4(U2v[idx]);
            F4ADD(rv, u1); F4ADD(rv, u2); F4ADD(rv, o4);
            outU[idx] = rv;
        }
    }
}

// ---------------- launch (serial, single stream, 9 kernels) ----------------
extern "C" void kernel_launch(void* const* d_in, const int* in_sizes, int n_in,
                              void* d_out, int out_size) {
    const float* user_emb   = (const float*)d_in[0];
    const float* entity_emb = (const float*)d_in[1];
    const float* rwm        = (const float*)d_in[2];
    const float* weight     = (const float*)d_in[3];
    const float* ivals      = (const float*)d_in[4];
    const int*   ehead      = (const int*)d_in[5];
    const int*   etail      = (const int*)d_in[6];
    const int*   etype      = (const int*)d_in[7];
    const int*   irows      = (const int*)d_in[8];
    const int*   icols      = (const int*)d_in[9];
    float* out = (float*)d_out;

    __half *pE0h, *pH1, *pH2, *pU1, *pU2;
    cudaGetSymbolAddress((void**)&pE0h, g_Eh0);
    cudaGetSymbolAddress((void**)&pH1, g_H1);
    cudaGetSymbolAddress((void**)&pH2, g_H2);
    cudaGetSymbolAddress((void**)&pU1, g_U1);
    cudaGetSymbolAddress((void**)&pU2, g_U2);

    __half* Esrc[NHOPS] = { pE0h, pH1, pH2 };
    __half* Udst[NHOPS] = { pU1, pU2, pU1 /*unused on last hop*/ };

    float4* resE = (float4*)out;
    float4* outU = (float4*)(out + (size_t)NE * CH);

    dim3 ggemm(NBM, SK);

    k_setup<<<(NSETUP + 255) / 256, 256>>>(ehead, irows, rwm, (const float4*)entity_emb);
    k_scan_lb<<<NSCAN, 1024>>>();
    k_fill<<<(NEDGE + NNZV + 255) / 256, 256>>>(ehead, etail, etype, irows, icols, ivals);

    for (int h = 0; h < NHOPS; h++) {
        __half* Ecur = Esrc[h];
        __half* Enxt = (h + 1 < NHOPS) ? Esrc[h + 1] : pH1 /*unused*/;
        k_gemm_mma<<<ggemm, 256>>>(Ecur + (size_t)RR0 * CH, (__half2*)Ecur);
        k_agg<<<EBLK + UBLK, 256>>>((const uint2*)Ecur, (uint2*)Enxt, (uint2*)Udst[h],
                                    resE, outU, (const float4*)weight,
                                    (const float4*)entity_emb, (const float4*)user_emb,
                                    (const uint2*)pH1, (const uint2*)pH2,
                                    (const uint2*)pU1, (const uint2*)pU2,
                                    h == 0 ? 1 : 0, h == NHOPS - 1 ? 1 : 0);
    }
}

// round 13
// speedup vs baseline: 1.0354x; 1.0354x over previous
#include <cuda_runtime.h>
#include <cuda_fp16.h>
#include <math.h>

// ---------------- problem constants ----------------
#define NE     100000
#define NU     50000
#define NTOT   (NE+NU)
#define NEDGE  2000000
#define NNZV   1000000
#define CH     128
#define C4     32
#define CHH2   64
#define RR0    42033
#define RR1    44630
#define RM     (RR1-RR0)     // 2597
#define RMP    2624
#define NREL   25
#define NHOPS  3
#define SK     8
#define NSCAN  147
#define EBLK   (NE/8)
#define UBLK   (NU/8)

// ---------------- device scratch ----------------
__device__ __half g_Eh0[NE*CH];            // fp16 input entity table
__device__ __half g_H1[NE*CH];             // hop-1/2 entity outputs
__device__ __half g_H2[NE*CH];
__device__ __half g_U1[NU*CH];             // hop-1/2 user outputs
__device__ __half g_U2[NU*CH];
__device__ __half g_Ah[RMP*RMP];
__device__ float g_regp[SK*RM*CH];
__device__ int   g_cnt[NTOT];
__device__ int   g_rowptr[NTOT+1];
__device__ int   g_cursor[NTOT];
__device__ int   g_pack[NEDGE];
__device__ int   g_ucol[NNZV];
__device__ float g_uval[NNZV];
__device__ unsigned long long g_lb[NSCAN];

// ---------------- helpers ----------------
__device__ __forceinline__ unsigned packh2(float x, float y) {
    __half2 t = __floats2half2_rn(x, y);
    return *reinterpret_cast<unsigned*>(&t);
}
__device__ __forceinline__ uint2 f4toh4(float4 v) {
    uint2 o; o.x = packh2(v.x, v.y); o.y = packh2(v.z, v.w);
    return o;
}
__device__ __forceinline__ float4 h4tof4(uint2 u) {
    __half2 a = *reinterpret_cast<__half2*>(&u.x);
    __half2 b = *reinterpret_cast<__half2*>(&u.y);
    float2 fa = __half22float2(a), fb = __half22float2(b);
    return make_float4(fa.x, fa.y, fb.x, fb.y);
}
__device__ __forceinline__ void cpa16(void* dst, const void* src) {
    unsigned d = (unsigned)__cvta_generic_to_shared(dst);
    asm volatile("cp.async.cg.shared.global [%0],[%1],16;\n" :: "r"(d), "l"(src));
}
#define CP_COMMIT() asm volatile("cp.async.commit_group;\n")
#define CP_WAIT1()  asm volatile("cp.async.wait_group 1;\n")
#define F4ADD(A,B) A.x+=B.x; A.y+=B.y; A.z+=B.z; A.w+=B.w;

// ---------------- fused setup: count + cvtA + cvtE ----------------
#define NCVE (NE*C4)
#define NCVA (RMP*RMP/4)
#define NSETUP (NEDGE + NNZV + NCVE + NCVA)

__global__ void k_setup(const int* __restrict__ ehead, const int* __restrict__ irows,
                        const float* __restrict__ rwm, const float4* __restrict__ E0) {
    int i = blockIdx.x * blockDim.x + threadIdx.x;
    if (i < NEDGE) {
        atomicAdd(&g_cnt[ehead[i]], 1);
    } else if (i < NEDGE + NNZV) {
        atomicAdd(&g_cnt[NE + irows[i - NEDGE]], 1);
    } else if (i < NEDGE + NNZV + NCVE) {
        int j = i - (NEDGE + NNZV);
        reinterpret_cast<uint2*>(g_Eh0)[j] = f4toh4(E0[j]);
    } else if (i < NSETUP) {
        int j = i - (NEDGE + NNZV + NCVE);
        int r = j / (RMP / 4), c = (j % (RMP / 4)) * 4;
        float v0 = 0, v1 = 0, v2 = 0, v3 = 0;
        if (r < RM) {
            const float* row = rwm + (size_t)r * RM;
            if (c + 0 < RM) v0 = row[c + 0];
            if (c + 1 < RM) v1 = row[c + 1];
            if (c + 2 < RM) v2 = row[c + 2];
            if (c + 3 < RM) v3 = row[c + 3];
        }
        *reinterpret_cast<uint2*>(&g_Ah[(size_t)r * RMP + c]) =
            f4toh4(make_float4(v0, v1, v2, v3));
    }
}

// ---------------- decoupled-lookback exclusive scan (self-resets g_cnt) ----------------
__global__ __launch_bounds__(1024)
void k_scan_lb() {
    __shared__ int s[1024];
    __shared__ int s_prefix;
    int b = blockIdx.x, t = threadIdx.x;
    int i = b * 1024 + t;
    int v = (i < NTOT) ? g_cnt[i] : 0;
    if (i < NTOT) g_cnt[i] = 0;
    s[t] = v;
    __syncthreads();
    #pragma unroll
    for (int off = 1; off < 1024; off <<= 1) {
        int tmp = (t >= off) ? s[t - off] : 0;
        __syncthreads();
        s[t] += tmp;
        __syncthreads();
    }
    int incl = s[t];
    int total = s[1023];
    if (t == 0) {
        if (b == 0) {
            atomicExch(&g_lb[0], (2ULL << 32) | (unsigned)total);
            s_prefix = 0;
        } else {
            atomicExch(&g_lb[b], (1ULL << 32) | (unsigned)total);
            long long ex = 0;
            int idx = b - 1;
            while (true) {
                unsigned long long pk;
                do { pk = atomicAdd(&g_lb[idx], 0ULL); } while ((pk >> 32) == 0);
                ex += (unsigned)pk;
                if ((pk >> 32) == 2ULL) break;
                idx--;
            }
            atomicExch(&g_lb[b], (2ULL << 32) | (unsigned)(ex + total));
            s_prefix = (int)ex;
        }
    }
    __syncthreads();
    int excl = s_prefix + incl - v;
    if (i < NTOT) { g_rowptr[i] = excl; g_cursor[i] = excl; }
    if (i == NTOT - 1) g_rowptr[NTOT] = NEDGE + NNZV;
}

__global__ void k_fill(const int* __restrict__ ehead, const int* __restrict__ etail,
                       const int* __restrict__ etype, const int* __restrict__ irows,
                       const int* __restrict__ icols, const float* __restrict__ ivals) {
    int i = blockIdx.x * blockDim.x + threadIdx.x;
    if (i < NSCAN) g_lb[i] = 0;
    if (i < NEDGE) {
        int pos = atomicAdd(&g_cursor[ehead[i]], 1);
        g_pack[pos] = etail[i] | ((etype[i] - 1) << 17);
    } else if (i < NEDGE + NNZV) {
        int k = i - NEDGE;
        int pos = atomicAdd(&g_cursor[NE + irows[k]], 1) - NEDGE;
        g_ucol[pos] = icols[k];
        g_uval[pos] = ivals[k];
    }
}

// ---------------- fp16 tensor-core region GEMM ----------------
__device__ __forceinline__ void ldsm4(unsigned* r, const void* p) {
    unsigned a = (unsigned)__cvta_generic_to_shared(p);
    asm volatile("ldmatrix.sync.aligned.m8n8.x4.shared.b16 {%0,%1,%2,%3},[%4];"
        : "=r"(r[0]), "=r"(r[1]), "=r"(r[2]), "=r"(r[3]) : "r"(a));
}
__device__ __forceinline__ void ldsm4t(unsigned* r, const void* p) {
    unsigned a = (unsigned)__cvta_generic_to_shared(p);
    asm volatile("ldmatrix.sync.aligned.m8n8.x4.trans.shared.b16 {%0,%1,%2,%3},[%4];"
        : "=r"(r[0]), "=r"(r[1]), "=r"(r[2]), "=r"(r[3]) : "r"(a));
}
__device__ __forceinline__ void mma_f16(float* d, const unsigned* a, const unsigned* b) {
    asm volatile("mma.sync.aligned.m16n8k16.row.col.f32.f16.f16.f32 "
        "{%0,%1,%2,%3},{%4,%5,%6,%7},{%8,%9},{%0,%1,%2,%3};"
        : "+f"(d[0]), "+f"(d[1]), "+f"(d[2]), "+f"(d[3])
        : "r"(a[0]), "r"(a[1]), "r"(a[2]), "r"(a[3]), "r"(b[0]), "r"(b[1]));
}

#define SA_STR 40
#define SB_STR 136

__global__ __launch_bounds__(256)
void k_gemm_mma(const __half* __restrict__ Bsrc) {
    __shared__ __align__(16) __half sA[2][64 * SA_STR];
    __shared__ __align__(16) __half sB[2][32 * SB_STR];
    int bm = blockIdx.x * 64;
    int sk = blockIdx.y;
    int kb = sk * 320;
    int ke = (sk == SK - 1) ? RMP : kb + 320;
    int iters = (ke - kb) >> 5;
    int tid = threadIdx.x, lane = tid & 31, w = tid >> 5;
    int wm = (w >> 1) * 16, wn = (w & 1) * 64;

    float acc[8][4];
    #pragma unroll
    for (int t = 0; t < 8; t++) { acc[t][0] = acc[t][1] = acc[t][2] = acc[t][3] = 0.f; }

    auto load_stage = [&](int s, int k0) {
        {
            int r = tid >> 2, c = (tid & 3) * 8;
            cpa16(&sA[s][r * SA_STR + c], &g_Ah[(size_t)(bm + r) * RMP + k0 + c]);
        }
        #pragma unroll
        for (int i2 = 0; i2 < 2; i2++) {
            int e = tid + i2 * 256;
            int r = e >> 4, c = (e & 15) * 8;
            cpa16(&sB[s][r * SB_STR + c], &Bsrc[(size_t)(k0 + r) * CH + c]);
        }
    };

    load_stage(0, kb);
    CP_COMMIT();

    for (int it = 0; it < iters; it++) {
        if (it + 1 < iters) load_stage((it + 1) & 1, kb + (it + 1) * 32);
        CP_COMMIT();
        CP_WAIT1();
        __syncthreads();
        int s = it & 1;
        #pragma unroll
        for (int kk = 0; kk < 32; kk += 16) {
            unsigned a[4];
            ldsm4(a, &sA[s][(wm + (lane & 15)) * SA_STR + kk + (lane >> 4) * 8]);
            #pragma unroll
            for (int nt = 0; nt < 4; nt++) {
                unsigned b[4];
                ldsm4t(b, &sB[s][(kk + (lane & 15)) * SB_STR + wn + nt * 16 + (lane >> 4) * 8]);
                mma_f16(acc[nt * 2],     a, b);
                mma_f16(acc[nt * 2 + 1], a, b + 2);
            }
        }
        __syncthreads();
    }

    float* C = g_regp + (size_t)sk * RM * CH;
    int g = lane >> 2, tig = lane & 3;
    #pragma unroll
    for (int t = 0; t < 8; t++) {
        int row = bm + wm + g, col = wn + t * 8 + tig * 2;
        if (row < RM)
            *reinterpret_cast<float2*>(&C[(size_t)row * CH + col]) = make_float2(acc[t][0], acc[t][1]);
        if (row + 8 < RM)
            *reinterpret_cast<float2*>(&C[(size_t)(row + 8) * CH + col]) = make_float2(acc[t][2], acc[t][3]);
    }
}

// blend: E[region] = 0.8*E + 0.2*(sum of SK partials); float4 partial reads
__global__ void k_blend(__half2* __restrict__ Eh) {
    int i = blockIdx.x * blockDim.x + threadIdx.x;   // one float4 (= 2 half2) per thread
    if (i < RM * C4) {
        float4 s = make_float4(0.f, 0.f, 0.f, 0.f);
        #pragma unroll
        for (int skk = 0; skk < SK; skk++) {
            float4 p = *reinterpret_cast<const float4*>(&g_regp[(size_t)skk * RM * CH + 4 * i]);
            s.x += p.x; s.y += p.y; s.z += p.z; s.w += p.w;
        }
        __half2* dst = &Eh[(size_t)RR0 * CHH2 + 2 * i];
        float2 e0 = __half22float2(dst[0]);
        float2 e1 = __half22float2(dst[1]);
        dst[0] = __floats2half2_rn(0.8f * e0.x + 0.2f * s.x, 0.8f * e0.y + 0.2f * s.y);
        dst[1] = __floats2half2_rn(0.8f * e1.x + 0.2f * s.z, 0.8f * e1.y + 0.2f * s.w);
    }
}

// ---------------- fused aggregate (frozen r9 loop) + folded final residual ------------
__global__ __launch_bounds__(256)
void k_agg(const uint2* __restrict__ E, uint2* __restrict__ Enext,
           uint2* __restrict__ Uout,
           float4* __restrict__ resE, float4* __restrict__ outU,
           const float4* __restrict__ W,
           const float4* __restrict__ E0f, const float4* __restrict__ U0f,
           const uint2* __restrict__ H1v, const uint2* __restrict__ H2v,
           const uint2* __restrict__ U1v, const uint2* __restrict__ U2v,
           int first, int last) {
    int lane = threadIdx.x & 31;
    int wline = threadIdx.x >> 5;

    if (blockIdx.x < EBLK) {
        __shared__ float4 sW[NREL * C4];
        for (int e = threadIdx.x; e < NREL * C4; e += 256) sW[e] = W[e];
        __syncthreads();

        int row = blockIdx.x * 8 + wline;
        int start = g_rowptr[row];
        int end   = g_rowptr[row + 1];

        float4 a0 = make_float4(0,0,0,0), a1 = make_float4(0,0,0,0);
        for (int base = start; base < end; base += 32) {
            int m = min(32, end - base);
            int p = (lane < m) ? g_pack[base + lane] : 0;
            int j = 0;
            for (; j + 4 <= m; j += 4) {
                int p0 = __shfl_sync(0xffffffffu, p, j);
                int p1 = __shfl_sync(0xffffffffu, p, j + 1);
                int p2 = __shfl_sync(0xffffffffu, p, j + 2);
                int p3 = __shfl_sync(0xffffffffu, p, j + 3);
                float4 e0 = h4tof4(E[(p0 & 0x1FFFF) * C4 + lane]);
                float4 e1 = h4tof4(E[(p1 & 0x1FFFF) * C4 + lane]);
                float4 e2 = h4tof4(E[(p2 & 0x1FFFF) * C4 + lane]);
                float4 e3 = h4tof4(E[(p3 & 0x1FFFF) * C4 + lane]);
                float4 w0 = sW[(p0 >> 17) * C4 + lane];
                float4 w1 = sW[(p1 >> 17) * C4 + lane];
                float4 w2 = sW[(p2 >> 17) * C4 + lane];
                float4 w3 = sW[(p3 >> 17) * C4 + lane];
                a0.x += e0.x*w0.x; a0.y += e0.y*w0.y; a0.z += e0.z*w0.z; a0.w += e0.w*w0.w;
                a1.x += e1.x*w1.x; a1.y += e1.y*w1.y; a1.z += e1.z*w1.z; a1.w += e1.w*w1.w;
                a0.x += e2.x*w2.x; a0.y += e2.y*w2.y; a0.z += e2.z*w2.z; a0.w += e2.w*w2.w;
                a1.x += e3.x*w3.x; a1.y += e3.y*w3.y; a1.z += e3.z*w3.z; a1.w += e3.w*w3.w;
            }
            for (; j < m; j++) {
                int pj = __shfl_sync(0xffffffffu, p, j);
                float4 ev = h4tof4(E[(pj & 0x1FFFF) * C4 + lane]);
                float4 w  = sW[(pj >> 17) * C4 + lane];
                a0.x += ev.x*w.x; a0.y += ev.y*w.y; a0.z += ev.z*w.z; a0.w += ev.w*w.w;
            }
        }
        float4 acc = make_float4(a0.x+a1.x, a0.y+a1.y, a0.z+a1.z, a0.w+a1.w);
        int cnt = end - start;
        float inv = cnt ? (1.f / (float)cnt) : 0.f;
        acc.x *= inv; acc.y *= inv; acc.z *= inv; acc.w *= inv;

        float ss = acc.x*acc.x + acc.y*acc.y + acc.z*acc.z + acc.w*acc.w;
        #pragma unroll
        for (int o = 16; o; o >>= 1) ss += __shfl_xor_sync(0xffffffffu, ss, o);
        float scale = 1.f / fmaxf(sqrtf(ss), 1e-12f);
        float4 o4 = make_float4(acc.x*scale, acc.y*scale, acc.z*scale, acc.w*scale);

        int idx = row * C4 + lane;
        bool region = (row >= RR0 && row < RR1);
        if (!last) {
            Enext[idx] = f4toh4(o4);
            if (region) {   // eager residual: hop-buffer copy gets blended next hop
                float4 rv = first ? E0f[idx] : resE[idx];
                F4ADD(rv, o4);
                resE[idx] = rv;
            }
        } else {            // final hop: write out = residual + o directly
            float4 rv;
            if (region) {
                rv = resE[idx];
            } else {
                rv = E0f[idx];
                float4 h1 = h4tof4(H1v[idx]);
                float4 h2 = h4tof4(H2v[idx]);
                F4ADD(rv, h1); F4ADD(rv, h2);
            }
            F4ADD(rv, o4);
            resE[idx] = rv;
        }
    } else {
        int row = (blockIdx.x - EBLK) * 8 + wline;
        int start = g_rowptr[NE + row]     - NEDGE;
        int end   = g_rowptr[NE + row + 1] - NEDGE;

        float4 a0 = make_float4(0,0,0,0), a1 = make_float4(0,0,0,0);
        for (int base = start; base < end; base += 32) {
            int m = min(32, end - base);
            int   c = (lane < m) ? g_ucol[base + lane] : 0;
            float v = (lane < m) ? g_uval[base + lane] : 0.f;
            int j = 0;
            for (; j + 4 <= m; j += 4) {
                int   c0 = __shfl_sync(0xffffffffu, c, j);
                int   c1 = __shfl_sync(0xffffffffu, c, j + 1);
                int   c2 = __shfl_sync(0xffffffffu, c, j + 2);
                int   c3 = __shfl_sync(0xffffffffu, c, j + 3);
                float v0 = __shfl_sync(0xffffffffu, v, j);
                float v1 = __shfl_sync(0xffffffffu, v, j + 1);
                float v2 = __shfl_sync(0xffffffffu, v, j + 2);
                float v3 = __shfl_sync(0xffffffffu, v, j + 3);
                float4 e0 = h4tof4(E[c0 * C4 + lane]);
                float4 e1 = h4tof4(E[c1 * C4 + lane]);
                float4 e2 = h4tof4(E[c2 * C4 + lane]);
                float4 e3 = h4tof4(E[c3 * C4 + lane]);
                a0.x += v0*e0.x; a0.y += v0*e0.y; a0.z += v0*e0.z; a0.w += v0*e0.w;
                a1.x += v1*e1.x; a1.y += v1*e1.y; a1.z += v1*e1.z; a1.w += v1*e1.w;
                a0.x += v2*e2.x; a0.y += v2*e2.y; a0.z += v2*e2.z; a0.w += v2*e2.w;
                a1.x += v3*e3.x; a1.y += v3*e3.y; a1.z += v3*e3.z; a1.w += v3*e3.w;
            }
            for (; j < m; j++) {
                int   cj = __shfl_sync(0xffffffffu, c, j);
                float vj = __shfl_sync(0xffffffffu, v, j);
                float4 ev = h4tof4(E[cj * C4 + lane]);
                a0.x += vj*ev.x; a0.y += vj*ev.y; a0.z += vj*ev.z; a0.w += vj*ev.w;
            }
        }
        float4 acc = make_float4(a0.x+a1.x, a0.y+a1.y, a0.z+a1.z, a0.w+a1.w);
        float ss = acc.x*acc.x + acc.y*acc.y + acc.z*acc.z + acc.w*acc.w;
        #pragma unroll
        for (int o = 16; o; o >>= 1) ss += __shfl_xor_sync(0xffffffffu, ss, o);
        float scale = 1.f / fmaxf(sqrtf(ss), 1e-12f);
        float4 o4 = make_float4(acc.x*scale, acc.y*scale, acc.z*scale, acc.w*scale);

        int idx = row * C4 + lane;
        if (!last) {
            Uout[idx] = f4toh4(o4);
        } else {
            float4 rv = U0f[idx];
            float4 u1 = h4tof4(U1v[idx]);
            float4 u2 = h4tof4(U2v[idx]);
            F4ADD(rv, u1); F4ADD(rv, u2); F4ADD(rv, o4);
            outU[idx] = rv;
        }
    }
}

// ---------------- launch (serial, single stream) ----------------
extern "C" void kernel_launch(void* const* d_in, const int* in_sizes, int n_in,
                              void* d_out, int out_size) {
    const float* user_emb   = (const float*)d_in[0];
    const float* entity_emb = (const float*)d_in[1];
    const float* rwm        = (const float*)d_in[2];
    const float* weight     = (const float*)d_in[3];
    const float* ivals      = (const float*)d_in[4];
    const int*   ehead      = (const int*)d_in[5];
    const int*   etail      = (const int*)d_in[6];
    const int*   etype      = (const int*)d_in[7];
    const int*   irows      = (const int*)d_in[8];
    const int*   icols      = (const int*)d_in[9];
    float* out = (float*)d_out;

    __half *pE0h, *pH1, *pH2, *pU1, *pU2;
    cudaGetSymbolAddress((void**)&pE0h, g_Eh0);
    cudaGetSymbolAddress((void**)&pH1, g_H1);
    cudaGetSymbolAddress((void**)&pH2, g_H2);
    cudaGetSymbolAddress((void**)&pU1, g_U1);
    cudaGetSymbolAddress((void**)&pU2, g_U2);

    __half* Esrc[NHOPS] = { pE0h, pH1, pH2 };
    __half* Udst[NHOPS] = { pU1, pU2, pU1 /*unused on last hop*/ };

    float4* resE = (float4*)out;
    float4* outU = (float4*)(out + (size_t)NE * CH);

    dim3 ggemm((RMP + 63) / 64, SK);

    k_setup<<<(NSETUP + 255) / 256, 256>>>(ehead, irows, rwm, (const float4*)entity_emb);
    k_scan_lb<<<NSCAN, 1024>>>();
    k_fill<<<(NEDGE + NNZV + 255) / 256, 256>>>(ehead, etail, etype, irows, icols, ivals);

    for (int h = 0; h < NHOPS; h++) {
        __half* Ecur = Esrc[h];
        __half* Enxt = (h + 1 < NHOPS) ? Esrc[h + 1] : pH1 /*unused*/;
        k_gemm_mma<<<ggemm, 256>>>(Ecur + (size_t)RR0 * CH);
        k_blend<<<(RM * C4 + 255) / 256, 256>>>((__half2*)Ecur);
        k_agg<<<EBLK + UBLK, 256>>>((const uint2*)Ecur, (uint2*)Enxt, (uint2*)Udst[h],
                                    resE, outU, (const float4*)weight,
                                    (const float4*)entity_emb, (const float4*)user_emb,
                                    (const uint2*)pH1, (const uint2*)pH2,
                                    (const uint2*)pU1, (const uint2*)pU2,
                                    h == 0 ? 1 : 0, h == NHOPS - 1 ? 1 : 0);
    }
}

// round 14
// speedup vs baseline: 1.0385x; 1.0029x over previous
#include <cuda_runtime.h>
#include <cuda_fp16.h>
#include <math.h>

// ---------------- problem constants ----------------
#define NE     100000
#define NU     50000
#define NTOT   (NE+NU)
#define NEDGE  2000000
#define NNZV   1000000
#define CH     128
#define C4     32
#define CHH2   64
#define RR0    42033
#define RR1    44630
#define RM     (RR1-RR0)     // 2597
#define RMP    2624
#define NREL   25
#define NHOPS  3
#define SK     8
#define NSCAN  147
#define EBLK   (NE/8)
#define UBLK   (NU/8)

// ---------------- device scratch ----------------
__device__ __half g_Eh0[NE*CH];            // fp16 input entity table
__device__ __half g_H1[NE*CH];             // hop-1/2 entity outputs
__device__ __half g_H2[NE*CH];
__device__ __half g_U1[NU*CH];             // hop-1/2 user outputs
__device__ __half g_U2[NU*CH];
__device__ __half g_Ah[RMP*RMP];
__device__ float g_regp[SK*RM*CH];
__device__ int   g_cnt[NTOT];
__device__ int   g_rowptr[NTOT+1];
__device__ int   g_cursor[NTOT];
__device__ int   g_pack[NEDGE];
__device__ int   g_ucol[NNZV];
__device__ float g_uval[NNZV];
__device__ unsigned long long g_lb[NSCAN];

// ---------------- helpers ----------------
__device__ __forceinline__ unsigned packh2(float x, float y) {
    __half2 t = __floats2half2_rn(x, y);
    return *reinterpret_cast<unsigned*>(&t);
}
__device__ __forceinline__ uint2 f4toh4(float4 v) {
    uint2 o; o.x = packh2(v.x, v.y); o.y = packh2(v.z, v.w);
    return o;
}
__device__ __forceinline__ float4 h4tof4(uint2 u) {
    __half2 a = *reinterpret_cast<__half2*>(&u.x);
    __half2 b = *reinterpret_cast<__half2*>(&u.y);
    float2 fa = __half22float2(a), fb = __half22float2(b);
    return make_float4(fa.x, fa.y, fb.x, fb.y);
}
__device__ __forceinline__ void cpa16(void* dst, const void* src) {
    unsigned d = (unsigned)__cvta_generic_to_shared(dst);
    asm volatile("cp.async.cg.shared.global [%0],[%1],16;\n" :: "r"(d), "l"(src));
}
#define CP_COMMIT() asm volatile("cp.async.commit_group;\n")
#define CP_WAIT2()  asm volatile("cp.async.wait_group 2;\n")
#define F4ADD(A,B) A.x+=B.x; A.y+=B.y; A.z+=B.z; A.w+=B.w;

// ---------------- fused setup: count + cvtA + cvtE ----------------
#define NCVE (NE*C4)
#define NCVA (RMP*RMP/4)
#define NSETUP (NEDGE + NNZV + NCVE + NCVA)

__global__ void k_setup(const int* __restrict__ ehead, const int* __restrict__ irows,
                        const float* __restrict__ rwm, const float4* __restrict__ E0) {
    int i = blockIdx.x * blockDim.x + threadIdx.x;
    if (i < NEDGE) {
        atomicAdd(&g_cnt[ehead[i]], 1);
    } else if (i < NEDGE + NNZV) {
        atomicAdd(&g_cnt[NE + irows[i - NEDGE]], 1);
    } else if (i < NEDGE + NNZV + NCVE) {
        int j = i - (NEDGE + NNZV);
        reinterpret_cast<uint2*>(g_Eh0)[j] = f4toh4(E0[j]);
    } else if (i < NSETUP) {
        int j = i - (NEDGE + NNZV + NCVE);
        int r = j / (RMP / 4), c = (j % (RMP / 4)) * 4;
        float v0 = 0, v1 = 0, v2 = 0, v3 = 0;
        if (r < RM) {
            const float* row = rwm + (size_t)r * RM;
            if (c + 0 < RM) v0 = row[c + 0];
            if (c + 1 < RM) v1 = row[c + 1];
            if (c + 2 < RM) v2 = row[c + 2];
            if (c + 3 < RM) v3 = row[c + 3];
        }
        *reinterpret_cast<uint2*>(&g_Ah[(size_t)r * RMP + c]) =
            f4toh4(make_float4(v0, v1, v2, v3));
    }
}

// ---------------- decoupled-lookback exclusive scan (shuffle-based, self-resets) -------
__global__ __launch_bounds__(1024)
void k_scan_lb() {
    __shared__ int swarp[32];
    __shared__ int s_prefix;
    int b = blockIdx.x, t = threadIdx.x;
    int lane = t & 31, wid = t >> 5;
    int i = b * 1024 + t;
    int v = (i < NTOT) ? g_cnt[i] : 0;
    if (i < NTOT) g_cnt[i] = 0;

    // warp-level inclusive scan
    int x = v;
    #pragma unroll
    for (int o = 1; o < 32; o <<= 1) {
        int y = __shfl_up_sync(0xffffffffu, x, o);
        if (lane >= o) x += y;
    }
    if (lane == 31) swarp[wid] = x;
    __syncthreads();
    if (wid == 0) {
        int y = swarp[lane];
        #pragma unroll
        for (int o = 1; o < 32; o <<= 1) {
            int z = __shfl_up_sync(0xffffffffu, y, o);
            if (lane >= o) y += z;
        }
        swarp[lane] = y;
    }
    __syncthreads();
    int incl = x + (wid ? swarp[wid - 1] : 0);
    int total = swarp[31];

    if (t == 0) {
        if (b == 0) {
            atomicExch(&g_lb[0], (2ULL << 32) | (unsigned)total);
            s_prefix = 0;
        } else {
            atomicExch(&g_lb[b], (1ULL << 32) | (unsigned)total);
            long long ex = 0;
            int idx = b - 1;
            while (true) {
                unsigned long long pk;
                do { pk = atomicAdd(&g_lb[idx], 0ULL); } while ((pk >> 32) == 0);
                ex += (unsigned)pk;
                if ((pk >> 32) == 2ULL) break;
                idx--;
            }
            atomicExch(&g_lb[b], (2ULL << 32) | (unsigned)(ex + total));
            s_prefix = (int)ex;
        }
    }
    __syncthreads();
    int excl = s_prefix + incl - v;
    if (i < NTOT) { g_rowptr[i] = excl; g_cursor[i] = excl; }
    if (i == NTOT - 1) g_rowptr[NTOT] = NEDGE + NNZV;
}

__global__ void k_fill(const int* __restrict__ ehead, const int* __restrict__ etail,
                       const int* __restrict__ etype, const int* __restrict__ irows,
                       const int* __restrict__ icols, const float* __restrict__ ivals) {
    int i = blockIdx.x * blockDim.x + threadIdx.x;
    if (i < NSCAN) g_lb[i] = 0;
    if (i < NEDGE) {
        int pos = atomicAdd(&g_cursor[ehead[i]], 1);
        g_pack[pos] = etail[i] | ((etype[i] - 1) << 17);
    } else if (i < NEDGE + NNZV) {
        int k = i - NEDGE;
        int pos = atomicAdd(&g_cursor[NE + irows[k]], 1) - NEDGE;
        g_ucol[pos] = icols[k];
        g_uval[pos] = ivals[k];
    }
}

// ---------------- fp16 tensor-core region GEMM, 3-stage cp.async pipeline --------------
__device__ __forceinline__ void ldsm4(unsigned* r, const void* p) {
    unsigned a = (unsigned)__cvta_generic_to_shared(p);
    asm volatile("ldmatrix.sync.aligned.m8n8.x4.shared.b16 {%0,%1,%2,%3},[%4];"
        : "=r"(r[0]), "=r"(r[1]), "=r"(r[2]), "=r"(r[3]) : "r"(a));
}
__device__ __forceinline__ void ldsm4t(unsigned* r, const void* p) {
    unsigned a = (unsigned)__cvta_generic_to_shared(p);
    asm volatile("ldmatrix.sync.aligned.m8n8.x4.trans.shared.b16 {%0,%1,%2,%3},[%4];"
        : "=r"(r[0]), "=r"(r[1]), "=r"(r[2]), "=r"(r[3]) : "r"(a));
}
__device__ __forceinline__ void mma_f16(float* d, const unsigned* a, const unsigned* b) {
    asm volatile("mma.sync.aligned.m16n8k16.row.col.f32.f16.f16.f32 "
        "{%0,%1,%2,%3},{%4,%5,%6,%7},{%8,%9},{%0,%1,%2,%3};"
        : "+f"(d[0]), "+f"(d[1]), "+f"(d[2]), "+f"(d[3])
        : "r"(a[0]), "r"(a[1]), "r"(a[2]), "r"(a[3]), "r"(b[0]), "r"(b[1]));
}

#define SA_STR 40
#define SB_STR 136

__global__ __launch_bounds__(256)
void k_gemm_mma(const __half* __restrict__ Bsrc) {
    __shared__ __align__(16) __half sA[3][64 * SA_STR];
    __shared__ __align__(16) __half sB[3][32 * SB_STR];
    int bm = blockIdx.x * 64;
    int sk = blockIdx.y;
    int kb = sk * 320;
    int ke = (sk == SK - 1) ? RMP : kb + 320;
    int iters = (ke - kb) >> 5;
    int tid = threadIdx.x, lane = tid & 31, w = tid >> 5;
    int wm = (w >> 1) * 16, wn = (w & 1) * 64;

    float acc[8][4];
    #pragma unroll
    for (int t = 0; t < 8; t++) { acc[t][0] = acc[t][1] = acc[t][2] = acc[t][3] = 0.f; }

    auto load_stage = [&](int s, int k0) {
        {
            int r = tid >> 2, c = (tid & 3) * 8;
            cpa16(&sA[s][r * SA_STR + c], &g_Ah[(size_t)(bm + r) * RMP + k0 + c]);
        }
        #pragma unroll
        for (int i2 = 0; i2 < 2; i2++) {
            int e = tid + i2 * 256;
            int r = e >> 4, c = (e & 15) * 8;
            cpa16(&sB[s][r * SB_STR + c], &Bsrc[(size_t)(k0 + r) * CH + c]);
        }
    };

    load_stage(0, kb);
    CP_COMMIT();
    if (iters > 1) load_stage(1, kb + 32);
    CP_COMMIT();

    for (int it = 0; it < iters; it++) {
        if (it + 2 < iters) load_stage((it + 2) % 3, kb + (it + 2) * 32);
        CP_COMMIT();
        CP_WAIT2();
        __syncthreads();
        int s = it % 3;
        #pragma unroll
        for (int kk = 0; kk < 32; kk += 16) {
            unsigned a[4];
            ldsm4(a, &sA[s][(wm + (lane & 15)) * SA_STR + kk + (lane >> 4) * 8]);
            #pragma unroll
            for (int nt = 0; nt < 4; nt++) {
                unsigned b[4];
                ldsm4t(b, &sB[s][(kk + (lane & 15)) * SB_STR + wn + nt * 16 + (lane >> 4) * 8]);
                mma_f16(acc[nt * 2],     a, b);
                mma_f16(acc[nt * 2 + 1], a, b + 2);
            }
        }
        __syncthreads();
    }

    float* C = g_regp + (size_t)sk * RM * CH;
    int g = lane >> 2, tig = lane & 3;
    #pragma unroll
    for (int t = 0; t < 8; t++) {
        int row = bm + wm + g, col = wn + t * 8 + tig * 2;
        if (row < RM)
            *reinterpret_cast<float2*>(&C[(size_t)row * CH + col]) = make_float2(acc[t][0], acc[t][1]);
        if (row + 8 < RM)
            *reinterpret_cast<float2*>(&C[(size_t)(row + 8) * CH + col]) = make_float2(acc[t][2], acc[t][3]);
    }
}

// blend: E[region] = 0.8*E + 0.2*(sum of SK partials); float4 partial reads
__global__ void k_blend(__half2* __restrict__ Eh) {
    int i = blockIdx.x * blockDim.x + threadIdx.x;   // one float4 (= 2 half2) per thread
    if (i < RM * C4) {
        float4 s = make_float4(0.f, 0.f, 0.f, 0.f);
        #pragma unroll
        for (int skk = 0; skk < SK; skk++) {
            float4 p = *reinterpret_cast<const float4*>(&g_regp[(size_t)skk * RM * CH + 4 * i]);
            s.x += p.x; s.y += p.y; s.z += p.z; s.w += p.w;
        }
        __half2* dst = &Eh[(size_t)RR0 * CHH2 + 2 * i];
        float2 e0 = __half22float2(dst[0]);
        float2 e1 = __half22float2(dst[1]);
        dst[0] = __floats2half2_rn(0.8f * e0.x + 0.2f * s.x, 0.8f * e0.y + 0.2f * s.y);
        dst[1] = __floats2half2_rn(0.8f * e1.x + 0.2f * s.z, 0.8f * e1.y + 0.2f * s.w);
    }
}

// ---------------- fused aggregate (frozen r9 loop) + folded final residual ------------
__global__ __launch_bounds__(256)
void k_agg(const uint2* __restrict__ E, uint2* __restrict__ Enext,
           uint2* __restrict__ Uout,
           float4* __restrict__ resE, float4* __restrict__ outU,
           const float4* __restrict__ W,
           const float4* __restrict__ E0f, const float4* __restrict__ U0f,
           const uint2* __restrict__ H1v, const uint2* __restrict__ H2v,
           const uint2* __restrict__ U1v, const uint2* __restrict__ U2v,
           int first, int last) {
    int lane = threadIdx.x & 31;
    int wline = threadIdx.x >> 5;

    if (blockIdx.x < EBLK) {
        __shared__ float4 sW[NREL * C4];
        for (int e = threadIdx.x; e < NREL * C4; e += 256) sW[e] = W[e];
        __syncthreads();

        int row = blockIdx.x * 8 + wline;
        int start = g_rowptr[row];
        int end   = g_rowptr[row + 1];

        float4 a0 = make_float4(0,0,0,0), a1 = make_float4(0,0,0,0);
        for (int base = start; base < end; base += 32) {
            int m = min(32, end - base);
            int p = (lane < m) ? g_pack[base + lane] : 0;
            int j = 0;
            for (; j + 4 <= m; j += 4) {
                int p0 = __shfl_sync(0xffffffffu, p, j);
                int p1 = __shfl_sync(0xffffffffu, p, j + 1);
                int p2 = __shfl_sync(0xffffffffu, p, j + 2);
                int p3 = __shfl_sync(0xffffffffu, p, j + 3);
                float4 e0 = h4tof4(E[(p0 & 0x1FFFF) * C4 + lane]);
                float4 e1 = h4tof4(E[(p1 & 0x1FFFF) * C4 + lane]);
                float4 e2 = h4tof4(E[(p2 & 0x1FFFF) * C4 + lane]);
                float4 e3 = h4tof4(E[(p3 & 0x1FFFF) * C4 + lane]);
                float4 w0 = sW[(p0 >> 17) * C4 + lane];
                float4 w1 = sW[(p1 >> 17) * C4 + lane];
                float4 w2 = sW[(p2 >> 17) * C4 + lane];
                float4 w3 = sW[(p3 >> 17) * C4 + lane];
                a0.x += e0.x*w0.x; a0.y += e0.y*w0.y; a0.z += e0.z*w0.z; a0.w += e0.w*w0.w;
                a1.x += e1.x*w1.x; a1.y += e1.y*w1.y; a1.z += e1.z*w1.z; a1.w += e1.w*w1.w;
                a0.x += e2.x*w2.x; a0.y += e2.y*w2.y; a0.z += e2.z*w2.z; a0.w += e2.w*w2.w;
                a1.x += e3.x*w3.x; a1.y += e3.y*w3.y; a1.z += e3.z*w3.z; a1.w += e3.w*w3.w;
            }
            for (; j < m; j++) {
                int pj = __shfl_sync(0xffffffffu, p, j);
                float4 ev = h4tof4(E[(pj & 0x1FFFF) * C4 + lane]);
                float4 w  = sW[(pj >> 17) * C4 + lane];
                a0.x += ev.x*w.x; a0.y += ev.y*w.y; a0.z += ev.z*w.z; a0.w += ev.w*w.w;
            }
        }
        float4 acc = make_float4(a0.x+a1.x, a0.y+a1.y, a0.z+a1.z, a0.w+a1.w);
        int cnt = end - start;
        float inv = cnt ? (1.f / (float)cnt) : 0.f;
        acc.x *= inv; acc.y *= inv; acc.z *= inv; acc.w *= inv;

        float ss = acc.x*acc.x + acc.y*acc.y + acc.z*acc.z + acc.w*acc.w;
        #pragma unroll
        for (int o = 16; o; o >>= 1) ss += __shfl_xor_sync(0xffffffffu, ss, o);
        float scale = 1.f / fmaxf(sqrtf(ss), 1e-12f);
        float4 o4 = make_float4(acc.x*scale, acc.y*scale, acc.z*scale, acc.w*scale);

        int idx = row * C4 + lane;
        bool region = (row >= RR0 && row < RR1);
        if (!last) {
            Enext[idx] = f4toh4(o4);
            if (region) {   // eager residual: hop-buffer copy gets blended next hop
                float4 rv = first ? E0f[idx] : resE[idx];
                F4ADD(rv, o4);
                resE[idx] = rv;
            }
        } else {            // final hop: write out = residual + o directly
            float4 rv;
            if (region) {
                rv = resE[idx];
            } else {
                rv = E0f[idx];
                float4 h1 = h4tof4(H1v[idx]);
                float4 h2 = h4tof4(H2v[idx]);
                F4ADD(rv, h1); F4ADD(rv, h2);
            }
            F4ADD(rv, o4);
            resE[idx] = rv;
        }
    } else {
        int row = (blockIdx.x - EBLK) * 8 + wline;
        int start = g_rowptr[NE + row]     - NEDGE;
        int end   = g_rowptr[NE + row + 1] - NEDGE;

        float4 a0 = make_float4(0,0,0,0), a1 = make_float4(0,0,0,0);
        for (int base = start; base < end; base += 32) {
            int m = min(32, end - base);
            int   c = (lane < m) ? g_ucol[base + lane] : 0;
            float v = (lane < m) ? g_uval[base + lane] : 0.f;
            int j = 0;
            for (; j + 4 <= m; j += 4) {
                int   c0 = __shfl_sync(0xffffffffu, c, j);
                int   c1 = __shfl_sync(0xffffffffu, c, j + 1);
                int   c2 = __shfl_sync(0xffffffffu, c, j + 2);
                int   c3 = __shfl_sync(0xffffffffu, c, j + 3);
                float v0 = __shfl_sync(0xffffffffu, v, j);
                float v1 = __shfl_sync(0xffffffffu, v, j + 1);
                float v2 = __shfl_sync(0xffffffffu, v, j + 2);
                float v3 = __shfl_sync(0xffffffffu, v, j + 3);
                float4 e0 = h4tof4(E[c0 * C4 + lane]);
                float4 e1 = h4tof4(E[c1 * C4 + lane]);
                float4 e2 = h4tof4(E[c2 * C4 + lane]);
                float4 e3 = h4tof4(E[c3 * C4 + lane]);
                a0.x += v0*e0.x; a0.y += v0*e0.y; a0.z += v0*e0.z; a0.w += v0*e0.w;
                a1.x += v1*e1.x; a1.y += v1*e1.y; a1.z += v1*e1.z; a1.w += v1*e1.w;
                a0.x += v2*e2.x; a0.y += v2*e2.y; a0.z += v2*e2.z; a0.w += v2*e2.w;
                a1.x += v3*e3.x; a1.y += v3*e3.y; a1.z += v3*e3.z; a1.w += v3*e3.w;
            }
            for (; j < m; j++) {
                int   cj = __shfl_sync(0xffffffffu, c, j);
                float vj = __shfl_sync(0xffffffffu, v, j);
                float4 ev = h4tof4(E[cj * C4 + lane]);
                a0.x += vj*ev.x; a0.y += vj*ev.y; a0.z += vj*ev.z; a0.w += vj*ev.w;
            }
        }
        float4 acc = make_float4(a0.x+a1.x, a0.y+a1.y, a0.z+a1.z, a0.w+a1.w);
        float ss = acc.x*acc.x + acc.y*acc.y + acc.z*acc.z + acc.w*acc.w;
        #pragma unroll
        for (int o = 16; o; o >>= 1) ss += __shfl_xor_sync(0xffffffffu, ss, o);
        float scale = 1.f / fmaxf(sqrtf(ss), 1e-12f);
        float4 o4 = make_float4(acc.x*scale, acc.y*scale, acc.z*scale, acc.w*scale);

        int idx = row * C4 + lane;
        if (!last) {
            Uout[idx] = f4toh4(o4);
        } else {
            float4 rv = U0f[idx];
            float4 u1 = h4tof4(U1v[idx]);
            float4 u2 = h4tof4(U2v[idx]);
            F4ADD(rv, u1); F4ADD(rv, u2); F4ADD(rv, o4);
            outU[idx] = rv;
        }
    }
}

// ---------------- launch (serial, single stream) ----------------
extern "C" void kernel_launch(void* const* d_in, const int* in_sizes, int n_in,
                              void* d_out, int out_size) {
    const float* user_emb   = (const float*)d_in[0];
    const float* entity_emb = (const float*)d_in[1];
    const float* rwm        = (const float*)d_in[2];
    const float* weight     = (const float*)d_in[3];
    const float* ivals      = (const float*)d_in[4];
    const int*   ehead      = (const int*)d_in[5];
    const int*   etail      = (const int*)d_in[6];
    const int*   etype      = (const int*)d_in[7];
    const int*   irows      = (const int*)d_in[8];
    const int*   icols      = (const int*)d_in[9];
    float* out = (float*)d_out;

    __half *pE0h, *pH1, *pH2, *pU1, *pU2;
    cudaGetSymbolAddress((void**)&pE0h, g_Eh0);
    cudaGetSymbolAddress((void**)&pH1, g_H1);
    cudaGetSymbolAddress((void**)&pH2, g_H2);
    cudaGetSymbolAddress((void**)&pU1, g_U1);
    cudaGetSymbolAddress((void**)&pU2, g_U2);

    __half* Esrc[NHOPS] = { pE0h, pH1, pH2 };
    __half* Udst[NHOPS] = { pU1, pU2, pU1 /*unused on last hop*/ };

    float4* resE = (float4*)out;
    float4* outU = (float4*)(out + (size_t)NE * CH);

    dim3 ggemm((RMP + 63) / 64, SK);

    k_setup<<<(NSETUP + 255) / 256, 256>>>(ehead, irows, rwm, (const float4*)entity_emb);
    k_scan_lb<<<NSCAN, 1024>>>();
    k_fill<<<(NEDGE + NNZV + 255) / 256, 256>>>(ehead, etail, etype, irows, icols, ivals);

    for (int h = 0; h < NHOPS; h++) {
        __half* Ecur = Esrc[h];
        __half* Enxt = (h + 1 < NHOPS) ? Esrc[h + 1] : pH1 /*unused*/;
        k_gemm_mma<<<ggemm, 256>>>(Ecur + (size_t)RR0 * CH);
        k_blend<<<(RM * C4 + 255) / 256, 256>>>((__half2*)Ecur);
        k_agg<<<EBLK + UBLK, 256>>>((const uint2*)Ecur, (uint2*)Enxt, (uint2*)Udst[h],
                                    resE, outU, (const float4*)weight,
                                    (const float4*)entity_emb, (const float4*)user_emb,
                                    (const uint2*)pH1, (const uint2*)pH2,
                                    (const uint2*)pU1, (const uint2*)pU2,
                                    h == 0 ? 1 : 0, h == NHOPS - 1 ? 1 : 0);
    }
}

// round 15
// speedup vs baseline: 1.0388x; 1.0003x over previous
#include <cuda_runtime.h>
#include <cuda_fp16.h>
#include <math.h>

// ---------------- problem constants ----------------
#define NE     100000
#define NU     50000
#define NTOT   (NE+NU)
#define NEDGE  2000000
#define NNZV   1000000
#define CH     128
#define C4     32
#define CHH2   64
#define RR0    42033
#define RR1    44630
#define RM     (RR1-RR0)     // 2597
#define RMP    2624
#define NREL   25
#define NHOPS  3
#define SK     8
#define NSCAN  147
#define EBLK   (NE/8)
#define UBLK   (NU/8)

// ---------------- device scratch ----------------
__device__ __half g_Eh0[NE*CH];            // fp16 input entity table
__device__ __half g_H1[NE*CH];             // hop-1/2 entity outputs
__device__ __half g_H2[NE*CH];
__device__ __half g_U1[NU*CH];             // hop-1/2 user outputs
__device__ __half g_U2[NU*CH];
__device__ __half g_Ah[RMP*RMP];
__device__ float g_regp[SK*RM*CH];
__device__ int   g_cnt[NTOT];
__device__ int   g_rowptr[NTOT+1];
__device__ int   g_cursor[NTOT];
__device__ int   g_pack[NEDGE];
__device__ int   g_ucol[NNZV];
__device__ float g_uval[NNZV];
__device__ unsigned long long g_lb[NSCAN];

// ---------------- helpers ----------------
__device__ __forceinline__ unsigned packh2(float x, float y) {
    __half2 t = __floats2half2_rn(x, y);
    return *reinterpret_cast<unsigned*>(&t);
}
__device__ __forceinline__ uint2 f4toh4(float4 v) {
    uint2 o; o.x = packh2(v.x, v.y); o.y = packh2(v.z, v.w);
    return o;
}
__device__ __forceinline__ float4 h4tof4(uint2 u) {
    __half2 a = *reinterpret_cast<__half2*>(&u.x);
    __half2 b = *reinterpret_cast<__half2*>(&u.y);
    float2 fa = __half22float2(a), fb = __half22float2(b);
    return make_float4(fa.x, fa.y, fb.x, fb.y);
}
__device__ __forceinline__ void cpa16(void* dst, const void* src) {
    unsigned d = (unsigned)__cvta_generic_to_shared(dst);
    asm volatile("cp.async.cg.shared.global [%0],[%1],16;\n" :: "r"(d), "l"(src));
}
#define CP_COMMIT() asm volatile("cp.async.commit_group;\n")
#define CP_WAIT2()  asm volatile("cp.async.wait_group 2;\n")
#define F4ADD(A,B) A.x+=B.x; A.y+=B.y; A.z+=B.z; A.w+=B.w;

// ---------------- fused setup: count + cvtA + cvtE ----------------
#define NCVE (NE*C4)
#define NCVA (RMP*RMP/4)
#define NSETUP (NEDGE + NNZV + NCVE + NCVA)

__global__ void k_setup(const int* __restrict__ ehead, const int* __restrict__ irows,
                        const float* __restrict__ rwm, const float4* __restrict__ E0) {
    int i = blockIdx.x * blockDim.x + threadIdx.x;
    if (i < NEDGE) {
        atomicAdd(&g_cnt[__ldcs(&ehead[i])], 1);
    } else if (i < NEDGE + NNZV) {
        atomicAdd(&g_cnt[NE + __ldcs(&irows[i - NEDGE])], 1);
    } else if (i < NEDGE + NNZV + NCVE) {
        int j = i - (NEDGE + NNZV);
        __stcs(&reinterpret_cast<uint2*>(g_Eh0)[j], f4toh4(__ldcs(&E0[j])));
    } else if (i < NSETUP) {
        int j = i - (NEDGE + NNZV + NCVE);
        int r = j / (RMP / 4), c = (j % (RMP / 4)) * 4;
        float v0 = 0, v1 = 0, v2 = 0, v3 = 0;
        if (r < RM) {
            const float* row = rwm + (size_t)r * RM;
            if (c + 0 < RM) v0 = __ldcs(&row[c + 0]);
            if (c + 1 < RM) v1 = __ldcs(&row[c + 1]);
            if (c + 2 < RM) v2 = __ldcs(&row[c + 2]);
            if (c + 3 < RM) v3 = __ldcs(&row[c + 3]);
        }
        __stcs(reinterpret_cast<uint2*>(&g_Ah[(size_t)r * RMP + c]),
               f4toh4(make_float4(v0, v1, v2, v3)));
    }
}

// ---------------- decoupled-lookback exclusive scan (shuffle-based, self-resets) -------
__global__ __launch_bounds__(1024)
void k_scan_lb() {
    __shared__ int swarp[32];
    __shared__ int s_prefix;
    int b = blockIdx.x, t = threadIdx.x;
    int lane = t & 31, wid = t >> 5;
    int i = b * 1024 + t;
    int v = (i < NTOT) ? g_cnt[i] : 0;
    if (i < NTOT) g_cnt[i] = 0;

    int x = v;
    #pragma unroll
    for (int o = 1; o < 32; o <<= 1) {
        int y = __shfl_up_sync(0xffffffffu, x, o);
        if (lane >= o) x += y;
    }
    if (lane == 31) swarp[wid] = x;
    __syncthreads();
    if (wid == 0) {
        int y = swarp[lane];
        #pragma unroll
        for (int o = 1; o < 32; o <<= 1) {
            int z = __shfl_up_sync(0xffffffffu, y, o);
            if (lane >= o) y += z;
        }
        swarp[lane] = y;
    }
    __syncthreads();
    int incl = x + (wid ? swarp[wid - 1] : 0);
    int total = swarp[31];

    if (t == 0) {
        if (b == 0) {
            atomicExch(&g_lb[0], (2ULL << 32) | (unsigned)total);
            s_prefix = 0;
        } else {
            atomicExch(&g_lb[b], (1ULL << 32) | (unsigned)total);
            long long ex = 0;
            int idx = b - 1;
            while (true) {
                unsigned long long pk;
                do { pk = atomicAdd(&g_lb[idx], 0ULL); } while ((pk >> 32) == 0);
                ex += (unsigned)pk;
                if ((pk >> 32) == 2ULL) break;
                idx--;
            }
            atomicExch(&g_lb[b], (2ULL << 32) | (unsigned)(ex + total));
            s_prefix = (int)ex;
        }
    }
    __syncthreads();
    int excl = s_prefix + incl - v;
    if (i < NTOT) { g_rowptr[i] = excl; g_cursor[i] = excl; }
    if (i == NTOT - 1) g_rowptr[NTOT] = NEDGE + NNZV;
}

__global__ void k_fill(const int* __restrict__ ehead, const int* __restrict__ etail,
                       const int* __restrict__ etype, const int* __restrict__ irows,
                       const int* __restrict__ icols, const float* __restrict__ ivals) {
    int i = blockIdx.x * blockDim.x + threadIdx.x;
    if (i < NSCAN) g_lb[i] = 0;
    if (i < NEDGE) {
        int pos = atomicAdd(&g_cursor[__ldcs(&ehead[i])], 1);
        __stcs(&g_pack[pos], __ldcs(&etail[i]) | ((__ldcs(&etype[i]) - 1) << 17));
    } else if (i < NEDGE + NNZV) {
        int k = i - NEDGE;
        int pos = atomicAdd(&g_cursor[NE + __ldcs(&irows[k])], 1) - NEDGE;
        __stcs(&g_ucol[pos], __ldcs(&icols[k]));
        __stcs(&g_uval[pos], __ldcs(&ivals[k]));
    }
}

// ---------------- fp16 tensor-core region GEMM, 3-stage cp.async pipeline --------------
__device__ __forceinline__ void ldsm4(unsigned* r, const void* p) {
    unsigned a = (unsigned)__cvta_generic_to_shared(p);
    asm volatile("ldmatrix.sync.aligned.m8n8.x4.shared.b16 {%0,%1,%2,%3},[%4];"
        : "=r"(r[0]), "=r"(r[1]), "=r"(r[2]), "=r"(r[3]) : "r"(a));
}
__device__ __forceinline__ void ldsm4t(unsigned* r, const void* p) {
    unsigned a = (unsigned)__cvta_generic_to_shared(p);
    asm volatile("ldmatrix.sync.aligned.m8n8.x4.trans.shared.b16 {%0,%1,%2,%3},[%4];"
        : "=r"(r[0]), "=r"(r[1]), "=r"(r[2]), "=r"(r[3]) : "r"(a));
}
__device__ __forceinline__ void mma_f16(float* d, const unsigned* a, const unsigned* b) {
    asm volatile("mma.sync.aligned.m16n8k16.row.col.f32.f16.f16.f32 "
        "{%0,%1,%2,%3},{%4,%5,%6,%7},{%8,%9},{%0,%1,%2,%3};"
        : "+f"(d[0]), "+f"(d[1]), "+f"(d[2]), "+f"(d[3])
        : "r"(a[0]), "r"(a[1]), "r"(a[2]), "r"(a[3]), "r"(b[0]), "r"(b[1]));
}

#define SA_STR 40
#define SB_STR 136

__global__ __launch_bounds__(256)
void k_gemm_mma(const __half* __restrict__ Bsrc) {
    __shared__ __align__(16) __half sA[3][64 * SA_STR];
    __shared__ __align__(16) __half sB[3][32 * SB_STR];
    int bm = blockIdx.x * 64;
    int sk = blockIdx.y;
    int kb = sk * 320;
    int ke = (sk == SK - 1) ? RMP : kb + 320;
    int iters = (ke - kb) >> 5;
    int tid = threadIdx.x, lane = tid & 31, w = tid >> 5;
    int wm = (w >> 1) * 16, wn = (w & 1) * 64;

    float acc[8][4];
    #pragma unroll
    for (int t = 0; t < 8; t++) { acc[t][0] = acc[t][1] = acc[t][2] = acc[t][3] = 0.f; }

    auto load_stage = [&](int s, int k0) {
        {
            int r = tid >> 2, c = (tid & 3) * 8;
            cpa16(&sA[s][r * SA_STR + c], &g_Ah[(size_t)(bm + r) * RMP + k0 + c]);
        }
        #pragma unroll
        for (int i2 = 0; i2 < 2; i2++) {
            int e = tid + i2 * 256;
            int r = e >> 4, c = (e & 15) * 8;
            cpa16(&sB[s][r * SB_STR + c], &Bsrc[(size_t)(k0 + r) * CH + c]);
        }
    };

    load_stage(0, kb);
    CP_COMMIT();
    if (iters > 1) load_stage(1, kb + 32);
    CP_COMMIT();

    for (int it = 0; it < iters; it++) {
        if (it + 2 < iters) load_stage((it + 2) % 3, kb + (it + 2) * 32);
        CP_COMMIT();
        CP_WAIT2();
        __syncthreads();
        int s = it % 3;
        #pragma unroll
        for (int kk = 0; kk < 32; kk += 16) {
            unsigned a[4];
            ldsm4(a, &sA[s][(wm + (lane & 15)) * SA_STR + kk + (lane >> 4) * 8]);
            #pragma unroll
            for (int nt = 0; nt < 4; nt++) {
                unsigned b[4];
                ldsm4t(b, &sB[s][(kk + (lane & 15)) * SB_STR + wn + nt * 16 + (lane >> 4) * 8]);
                mma_f16(acc[nt * 2],     a, b);
                mma_f16(acc[nt * 2 + 1], a, b + 2);
            }
        }
        __syncthreads();
    }

    float* C = g_regp + (size_t)sk * RM * CH;
    int g = lane >> 2, tig = lane & 3;
    #pragma unroll
    for (int t = 0; t < 8; t++) {
        int row = bm + wm + g, col = wn + t * 8 + tig * 2;
        if (row < RM)
            *reinterpret_cast<float2*>(&C[(size_t)row * CH + col]) = make_float2(acc[t][0], acc[t][1]);
        if (row + 8 < RM)
            *reinterpret_cast<float2*>(&C[(size_t)(row + 8) * CH + col]) = make_float2(acc[t][2], acc[t][3]);
    }
}

// blend: E[region] = 0.8*E + 0.2*(sum of SK partials); float4 partial reads
__global__ void k_blend(__half2* __restrict__ Eh) {
    int i = blockIdx.x * blockDim.x + threadIdx.x;
    if (i < RM * C4) {
        float4 s = make_float4(0.f, 0.f, 0.f, 0.f);
        #pragma unroll
        for (int skk = 0; skk < SK; skk++) {
            float4 p = __ldcs(reinterpret_cast<const float4*>(&g_regp[(size_t)skk * RM * CH + 4 * i]));
            s.x += p.x; s.y += p.y; s.z += p.z; s.w += p.w;
        }
        __half2* dst = &Eh[(size_t)RR0 * CHH2 + 2 * i];
        float2 e0 = __half22float2(dst[0]);
        float2 e1 = __half22float2(dst[1]);
        dst[0] = __floats2half2_rn(0.8f * e0.x + 0.2f * s.x, 0.8f * e0.y + 0.2f * s.y);
        dst[1] = __floats2half2_rn(0.8f * e1.x + 0.2f * s.z, 0.8f * e1.y + 0.2f * s.w);
    }
}

// ---------------- fused aggregate (frozen loop) + folded final residual ---------------
// streaming (.cs) hints on all non-reused traffic keep the fp16 gather table L2-resident
__global__ __launch_bounds__(256)
void k_agg(const uint2* __restrict__ E, uint2* __restrict__ Enext,
           uint2* __restrict__ Uout,
           float4* __restrict__ resE, float4* __restrict__ outU,
           const float4* __restrict__ W,
           const float4* __restrict__ E0f, const float4* __restrict__ U0f,
           const uint2* __restrict__ H1v, const uint2* __restrict__ H2v,
           const uint2* __restrict__ U1v, const uint2* __restrict__ U2v,
           int first, int last) {
    int lane = threadIdx.x & 31;
    int wline = threadIdx.x >> 5;

    if (blockIdx.x < EBLK) {
        __shared__ float4 sW[NREL * C4];
        for (int e = threadIdx.x; e < NREL * C4; e += 256) sW[e] = W[e];
        __syncthreads();

        int row = blockIdx.x * 8 + wline;
        int start = g_rowptr[row];
        int end   = g_rowptr[row + 1];

        float4 a0 = make_float4(0,0,0,0), a1 = make_float4(0,0,0,0);
        for (int base = start; base < end; base += 32) {
            int m = min(32, end - base);
            int p = (lane < m) ? __ldcs(&g_pack[base + lane]) : 0;
            int j = 0;
            for (; j + 4 <= m; j += 4) {
                int p0 = __shfl_sync(0xffffffffu, p, j);
                int p1 = __shfl_sync(0xffffffffu, p, j + 1);
                int p2 = __shfl_sync(0xffffffffu, p, j + 2);
                int p3 = __shfl_sync(0xffffffffu, p, j + 3);
                float4 e0 = h4tof4(E[(p0 & 0x1FFFF) * C4 + lane]);
                float4 e1 = h4tof4(E[(p1 & 0x1FFFF) * C4 + lane]);
                float4 e2 = h4tof4(E[(p2 & 0x1FFFF) * C4 + lane]);
                float4 e3 = h4tof4(E[(p3 & 0x1FFFF) * C4 + lane]);
                float4 w0 = sW[(p0 >> 17) * C4 + lane];
                float4 w1 = sW[(p1 >> 17) * C4 + lane];
                float4 w2 = sW[(p2 >> 17) * C4 + lane];
                float4 w3 = sW[(p3 >> 17) * C4 + lane];
                a0.x += e0.x*w0.x; a0.y += e0.y*w0.y; a0.z += e0.z*w0.z; a0.w += e0.w*w0.w;
                a1.x += e1.x*w1.x; a1.y += e1.y*w1.y; a1.z += e1.z*w1.z; a1.w += e1.w*w1.w;
                a0.x += e2.x*w2.x; a0.y += e2.y*w2.y; a0.z += e2.z*w2.z; a0.w += e2.w*w2.w;
                a1.x += e3.x*w3.x; a1.y += e3.y*w3.y; a1.z += e3.z*w3.z; a1.w += e3.w*w3.w;
            }
            for (; j < m; j++) {
                int pj = __shfl_sync(0xffffffffu, p, j);
                float4 ev = h4tof4(E[(pj & 0x1FFFF) * C4 + lane]);
                float4 w  = sW[(pj >> 17) * C4 + lane];
                a0.x += ev.x*w.x; a0.y += ev.y*w.y; a0.z += ev.z*w.z; a0.w += ev.w*w.w;
            }
        }
        float4 acc = make_float4(a0.x+a1.x, a0.y+a1.y, a0.z+a1.z, a0.w+a1.w);
        int cnt = end - start;
        float inv = cnt ? (1.f / (float)cnt) : 0.f;
        acc.x *= inv; acc.y *= inv; acc.z *= inv; acc.w *= inv;

        float ss = acc.x*acc.x + acc.y*acc.y + acc.z*acc.z + acc.w*acc.w;
        #pragma unroll
        for (int o = 16; o; o >>= 1) ss += __shfl_xor_sync(0xffffffffu, ss, o);
        float scale = 1.f / fmaxf(sqrtf(ss), 1e-12f);
        float4 o4 = make_float4(acc.x*scale, acc.y*scale, acc.z*scale, acc.w*scale);

        int idx = row * C4 + lane;
        bool region = (row >= RR0 && row < RR1);
        if (!last) {
            Enext[idx] = f4toh4(o4);   // reused next hop: default policy
            if (region) {
                float4 rv = first ? __ldcs(&E0f[idx]) : resE[idx];
                F4ADD(rv, o4);
                __stcs(&resE[idx], rv);
            }
        } else {
            float4 rv;
            if (region) {
                rv = resE[idx];
            } else {
                rv = __ldcs(&E0f[idx]);
                float4 h1 = h4tof4(__ldcs(&H1v[idx]));
                float4 h2 = h4tof4(__ldcs(&H2v[idx]));
                F4ADD(rv, h1); F4ADD(rv, h2);
            }
            F4ADD(rv, o4);
            __stcs(&resE[idx], rv);
        }
    } else {
        int row = (blockIdx.x - EBLK) * 8 + wline;
        int start = g_rowptr[NE + row]     - NEDGE;
        int end   = g_rowptr[NE + row + 1] - NEDGE;

        float4 a0 = make_float4(0,0,0,0), a1 = make_float4(0,0,0,0);
        for (int base = start; base < end; base += 32) {
            int m = min(32, end - base);
            int   c = (lane < m) ? __ldcs(&g_ucol[base + lane]) : 0;
            float v = (lane < m) ? __ldcs(&g_uval[base + lane]) : 0.f;
            int j = 0;
            for (; j + 4 <= m; j += 4) {
                int   c0 = __shfl_sync(0xffffffffu, c, j);
                int   c1 = __shfl_sync(0xffffffffu, c, j + 1);
                int   c2 = __shfl_sync(0xffffffffu, c, j + 2);
                int   c3 = __shfl_sync(0xffffffffu, c, j + 3);
                float v0 = __shfl_sync(0xffffffffu, v, j);
                float v1 = __shfl_sync(0xffffffffu, v, j + 1);
                float v2 = __shfl_sync(0xffffffffu, v, j + 2);
                float v3 = __shfl_sync(0xffffffffu, v, j + 3);
                float4 e0 = h4tof4(E[c0 * C4 + lane]);
                float4 e1 = h4tof4(E[c1 * C4 + lane]);
                float4 e2 = h4tof4(E[c2 * C4 + lane]);
                float4 e3 = h4tof4(E[c3 * C4 + lane]);
                a0.x += v0*e0.x; a0.y += v0*e0.y; a0.z += v0*e0.z; a0.w += v0*e0.w;
                a1.x += v1*e1.x; a1.y += v1*e1.y; a1.z += v1*e1.z; a1.w += v1*e1.w;
                a0.x += v2*e2.x; a0.y += v2*e2.y; a0.z += v2*e2.z; a0.w += v2*e2.w;
                a1.x += v3*e3.x; a1.y += v3*e3.y; a1.z += v3*e3.z; a1.w += v3*e3.w;
            }
            for (; j < m; j++) {
                int   cj = __shfl_sync(0xffffffffu, c, j);
                float vj = __shfl_sync(0xffffffffu, v, j);
                float4 ev = h4tof4(E[cj * C4 + lane]);
                a0.x += vj*ev.x; a0.y += vj*ev.y; a0.z += vj*ev.z; a0.w += vj*ev.w;
            }
        }
        float4 acc = make_float4(a0.x+a1.x, a0.y+a1.y, a0.z+a1.z, a0.w+a1.w);
        float ss = acc.x*acc.x + acc.y*acc.y + acc.z*acc.z + acc.w*acc.w;
        #pragma unroll
        for (int o = 16; o; o >>= 1) ss += __shfl_xor_sync(0xffffffffu, ss, o);
        float scale = 1.f / fmaxf(sqrtf(ss), 1e-12f);
        float4 o4 = make_float4(acc.x*scale, acc.y*scale, acc.z*scale, acc.w*scale);

        int idx = row * C4 + lane;
        if (!last) {
            __stcs(&Uout[idx], f4toh4(o4));
        } else {
            float4 rv = __ldcs(&U0f[idx]);
            float4 u1 = h4tof4(__ldcs(&U1v[idx]));
            float4 u2 = h4tof4(__ldcs(&U2v[idx]));
            F4ADD(rv, u1); F4ADD(rv, u2); F4ADD(rv, o4);
            __stcs(&outU[idx], rv);
        }
    }
}

// ---------------- launch (serial, single stream) ----------------
extern "C" void kernel_launch(void* const* d_in, const int* in_sizes, int n_in,
                              void* d_out, int out_size) {
    const float* user_emb   = (const float*)d_in[0];
    const float* entity_emb = (const float*)d_in[1];
    const float* rwm        = (const float*)d_in[2];
    const float* weight     = (const float*)d_in[3];
    const float* ivals      = (const float*)d_in[4];
    const int*   ehead      = (const int*)d_in[5];
    const int*   etail      = (const int*)d_in[6];
    const int*   etype      = (const int*)d_in[7];
    const int*   irows      = (const int*)d_in[8];
    const int*   icols      = (const int*)d_in[9];
    float* out = (float*)d_out;

    __half *pE0h, *pH1, *pH2, *pU1, *pU2;
    cudaGetSymbolAddress((void**)&pE0h, g_Eh0);
    cudaGetSymbolAddress((void**)&pH1, g_H1);
    cudaGetSymbolAddress((void**)&pH2, g_H2);
    cudaGetSymbolAddress((void**)&pU1, g_U1);
    cudaGetSymbolAddress((void**)&pU2, g_U2);

    __half* Esrc[NHOPS] = { pE0h, pH1, pH2 };
    __half* Udst[NHOPS] = { pU1, pU2, pU1 /*unused on last hop*/ };

    float4* resE = (float4*)out;
    float4* outU = (float4*)(out + (size_t)NE * CH);

    dim3 ggemm((RMP + 63) / 64, SK);

    k_setup<<<(NSETUP + 255) / 256, 256>>>(ehead, irows, rwm, (const float4*)entity_emb);
    k_scan_lb<<<NSCAN, 1024>>>();
    k_fill<<<(NEDGE + NNZV + 255) / 256, 256>>>(ehead, etail, etype, irows, icols, ivals);

    for (int h = 0; h < NHOPS; h++) {
        __half* Ecur = Esrc[h];
        __half* Enxt = (h + 1 < NHOPS) ? Esrc[h + 1] : pH1 /*unused*/;
        k_gemm_mma<<<ggemm, 256>>>(Ecur + (size_t)RR0 * CH);
        k_blend<<<(RM * C4 + 255) / 256, 256>>>((__half2*)Ecur);
        k_agg<<<EBLK + UBLK, 256>>>((const uint2*)Ecur, (uint2*)Enxt, (uint2*)Udst[h],
                                    resE, outU, (const float4*)weight,
                                    (const float4*)entity_emb, (const float4*)user_emb,
                                    (const uint2*)pH1, (const uint2*)pH2,
                                    (const uint2*)pU1, (const uint2*)pU2,
                                    h == 0 ? 1 : 0, h == NHOPS - 1 ? 1 : 0);
    }
}